// round 1
// baseline (speedup 1.0000x reference)
#include <cuda_runtime.h>

#define N_NODES  50000
#define N_EDGES  600000
#define N_GRAPHS 256
#define C        128

// ---------------- scratch (device globals; no allocations allowed) ----------
__device__ int   d_deg[N_NODES];
__device__ int   d_rowptr[N_NODES + 1];
__device__ int   d_fill[N_NODES];
__device__ int   d_esrc[N_EDGES];
__device__ float d_deginv[N_NODES];
__device__ float d_agg[N_NODES * C];
__device__ float d_h0[N_NODES * C];
__device__ float d_h1[N_NODES * C];
__device__ float d_WT[4][256 * 128];     // per-layer [k][co], k<128 -> W_l, k>=128 -> W_r
__device__ float d_gsum[N_GRAPHS * C];
__device__ float d_gcnt[N_GRAPHS];

// ---------------- init: zero counters / accumulators ------------------------
__global__ void k_init() {
    int i = blockIdx.x * blockDim.x + threadIdx.x;
    int stride = gridDim.x * blockDim.x;
    for (int j = i; j < N_NODES; j += stride) { d_deg[j] = 0; d_fill[j] = 0; }
    for (int j = i; j < N_GRAPHS * C; j += stride) d_gsum[j] = 0.f;
    for (int j = i; j < N_GRAPHS; j += stride) d_gcnt[j] = 0.f;
}

// ---------------- degree histogram ------------------------------------------
__global__ void k_hist(const int* __restrict__ tgt) {
    int e = blockIdx.x * blockDim.x + threadIdx.x;
    if (e < N_EDGES) atomicAdd(&d_deg[tgt[e]], 1);
}

// ---------------- exclusive scan (single block, 1024 threads) ---------------
__global__ void k_scan() {
    __shared__ int sums[1024];
    const int CH = (N_NODES + 1023) / 1024;   // 49
    int t = threadIdx.x;
    int base = t * CH;
    int s = 0;
    for (int i = base; i < base + CH && i < N_NODES; i++) s += d_deg[i];
    sums[t] = s;
    __syncthreads();
    for (int off = 1; off < 1024; off <<= 1) {
        int v = 0;
        if (t >= off) v = sums[t - off];
        __syncthreads();
        if (t >= off) sums[t] += v;
        __syncthreads();
    }
    int run = (t > 0) ? sums[t - 1] : 0;
    for (int i = base; i < base + CH && i < N_NODES; i++) {
        d_rowptr[i] = run;
        int dg = d_deg[i];
        d_deginv[i] = 1.0f / (float)max(dg, 1);
        run += dg;
    }
    if (N_NODES >= base && N_NODES < base + CH) d_rowptr[N_NODES] = run;
}

// ---------------- counting-sort edges by target (CSR fill) ------------------
__global__ void k_fill(const int* __restrict__ src, const int* __restrict__ tgt) {
    int e = blockIdx.x * blockDim.x + threadIdx.x;
    if (e < N_EDGES) {
        int t = tgt[e];
        int slot = atomicAdd(&d_fill[t], 1);
        d_esrc[d_rowptr[t] + slot] = src[e];
    }
}

// ---------------- weight transpose to k-major [256][128] --------------------
__global__ void k_wtrans(const float* __restrict__ wl, const float* __restrict__ wr, int layer) {
    int k = blockIdx.x;          // 0..255
    int co = threadIdx.x;        // 0..127
    float v = (k < 128) ? wl[co * 128 + k] : wr[co * 128 + (k - 128)];
    d_WT[layer][k * 128 + co] = v;
}

// ---------------- mean aggregation via CSR ----------------------------------
// one block per node, 128 threads = 128 channels
__global__ void k_agg(const float* __restrict__ xext, int insel) {
    const float* xin = (insel == 0) ? xext : ((insel == 1) ? d_h0 : d_h1);
    int n = blockIdx.x;
    int c = threadIdx.x;
    int s0 = d_rowptr[n], s1 = d_rowptr[n + 1];
    float acc = 0.f;
    #pragma unroll 4
    for (int e = s0; e < s1; e++) {
        acc += __ldg(&xin[d_esrc[e] * C + c]);
    }
    d_agg[n * C + c] = acc * d_deginv[n];
}

// ---------------- fused SAGE linear: out = relu([agg|x] @ WT + b) -----------
#define BM 128
#define BK 16
__global__ __launch_bounds__(256) void k_gemm(
    const float* __restrict__ xext, int insel, int outsel, int layer,
    const float* __restrict__ bias)
{
    const float* Ax = (insel == 0) ? xext : ((insel == 1) ? d_h0 : d_h1);
    float* out = (outsel == 1) ? d_h0 : d_h1;
    const float* WT = d_WT[layer];

    __shared__ float As[BK][BM + 4];
    __shared__ float Ws[BK][BM];

    int tid = threadIdx.x;
    int tx = tid & 15;       // output-channel tile index
    int ty = tid >> 4;       // row tile index
    int rowBase = blockIdx.x * BM;

    float acc[8][8];
    #pragma unroll
    for (int i = 0; i < 8; i++)
        #pragma unroll
        for (int j = 0; j < 8; j++) acc[i][j] = 0.f;

    for (int k0 = 0; k0 < 256; k0 += BK) {
        const float* Asrc = (k0 < 128) ? d_agg : Ax;
        int kloc = k0 & 127;

        // load A tile (128 rows x 16 k), transposed into As[k][m]
        #pragma unroll
        for (int f = tid; f < (BM * BK) / 4; f += 256) {
            int r = f >> 2;
            int kq = (f & 3) << 2;
            int grow = rowBase + r;
            float4 v = make_float4(0.f, 0.f, 0.f, 0.f);
            if (grow < N_NODES)
                v = *(const float4*)&Asrc[grow * C + kloc + kq];
            As[kq + 0][r] = v.x;
            As[kq + 1][r] = v.y;
            As[kq + 2][r] = v.z;
            As[kq + 3][r] = v.w;
        }
        // load W tile (16 k x 128 co), already k-major -> coalesced
        #pragma unroll
        for (int f = tid; f < (BK * 128) / 4; f += 256) {
            int kk = f >> 5;
            int cq = (f & 31) << 2;
            *(float4*)&Ws[kk][cq] = *(const float4*)&WT[(k0 + kk) * 128 + cq];
        }
        __syncthreads();

        #pragma unroll
        for (int kk = 0; kk < BK; kk++) {
            float4 a0 = *(const float4*)&As[kk][ty * 8];
            float4 a1 = *(const float4*)&As[kk][ty * 8 + 4];
            float4 w0 = *(const float4*)&Ws[kk][tx * 8];
            float4 w1 = *(const float4*)&Ws[kk][tx * 8 + 4];
            float aR[8] = {a0.x, a0.y, a0.z, a0.w, a1.x, a1.y, a1.z, a1.w};
            float wR[8] = {w0.x, w0.y, w0.z, w0.w, w1.x, w1.y, w1.z, w1.w};
            #pragma unroll
            for (int i = 0; i < 8; i++)
                #pragma unroll
                for (int j = 0; j < 8; j++)
                    acc[i][j] += aR[i] * wR[j];
        }
        __syncthreads();
    }

    float4 bv0 = *(const float4*)&bias[tx * 8];
    float4 bv1 = *(const float4*)&bias[tx * 8 + 4];
    float bb[8] = {bv0.x, bv0.y, bv0.z, bv0.w, bv1.x, bv1.y, bv1.z, bv1.w};

    #pragma unroll
    for (int i = 0; i < 8; i++) {
        int grow = rowBase + ty * 8 + i;
        if (grow < N_NODES) {
            float4 o0, o1;
            o0.x = fmaxf(acc[i][0] + bb[0], 0.f);
            o0.y = fmaxf(acc[i][1] + bb[1], 0.f);
            o0.z = fmaxf(acc[i][2] + bb[2], 0.f);
            o0.w = fmaxf(acc[i][3] + bb[3], 0.f);
            o1.x = fmaxf(acc[i][4] + bb[4], 0.f);
            o1.y = fmaxf(acc[i][5] + bb[5], 0.f);
            o1.z = fmaxf(acc[i][6] + bb[6], 0.f);
            o1.w = fmaxf(acc[i][7] + bb[7], 0.f);
            *(float4*)&out[grow * C + tx * 8] = o0;
            *(float4*)&out[grow * C + tx * 8 + 4] = o1;
        }
    }
}

// ---------------- graph mean pooling (sum + count via atomics) --------------
__global__ void k_pool(const int* __restrict__ batch) {
    int n = blockIdx.x;
    int c = threadIdx.x;
    int g = batch[n];
    atomicAdd(&d_gsum[g * C + c], d_h1[n * C + c]);
    if (c == 0) atomicAdd(&d_gcnt[g], 1.0f);
}

// ---------------- classifier: [root_emb | graph_mean] @ w_cls^T + b ---------
__global__ void k_final(const int* __restrict__ root,
                        const float* __restrict__ wcls,
                        const float* __restrict__ bcls,
                        float* __restrict__ out)
{
    int g = blockIdx.x;
    int c = threadIdx.x;   // 128
    float rv = d_h1[root[g] * C + c];
    float gm = d_gsum[g * C + c] / fmaxf(d_gcnt[g], 1.0f);
    __shared__ float red[2][4];
    float p0 = rv * wcls[0 * 256 + c] + gm * wcls[0 * 256 + 128 + c];
    float p1 = rv * wcls[1 * 256 + c] + gm * wcls[1 * 256 + 128 + c];
    #pragma unroll
    for (int off = 16; off > 0; off >>= 1) {
        p0 += __shfl_down_sync(0xffffffffu, p0, off);
        p1 += __shfl_down_sync(0xffffffffu, p1, off);
    }
    if ((c & 31) == 0) { red[0][c >> 5] = p0; red[1][c >> 5] = p1; }
    __syncthreads();
    if (c == 0) {
        out[g * 2 + 0] = red[0][0] + red[0][1] + red[0][2] + red[0][3] + bcls[0];
        out[g * 2 + 1] = red[1][0] + red[1][1] + red[1][2] + red[1][3] + bcls[1];
    }
}

// ---------------- launch ----------------------------------------------------
extern "C" void kernel_launch(void* const* d_in, const int* in_sizes, int n_in,
                              void* d_out, int out_size)
{
    const float* x     = (const float*)d_in[0];
    const int*   eidx  = (const int*)d_in[1];
    const int*   src   = eidx;
    const int*   tgt   = eidx + N_EDGES;
    const int*   root  = (const int*)d_in[2];
    const int*   batch = (const int*)d_in[3];
    const float* wl[4] = {(const float*)d_in[4],  (const float*)d_in[7],
                          (const float*)d_in[10], (const float*)d_in[13]};
    const float* bl[4] = {(const float*)d_in[5],  (const float*)d_in[8],
                          (const float*)d_in[11], (const float*)d_in[14]};
    const float* wr[4] = {(const float*)d_in[6],  (const float*)d_in[9],
                          (const float*)d_in[12], (const float*)d_in[15]};
    const float* wcls  = (const float*)d_in[16];
    const float* bcls  = (const float*)d_in[17];
    float* out = (float*)d_out;

    (void)in_sizes; (void)n_in; (void)out_size;

    // structure build
    k_init<<<256, 256>>>();
    k_hist<<<(N_EDGES + 255) / 256, 256>>>(tgt);
    k_scan<<<1, 1024>>>();
    k_fill<<<(N_EDGES + 255) / 256, 256>>>(src, tgt);

    // weight transposes (k-major concat of [W_l; W_r])
    for (int l = 0; l < 4; l++)
        k_wtrans<<<256, 128>>>(wl[l], wr[l], l);

    const int GEMM_GRID = (N_NODES + BM - 1) / BM;   // 391

    // layer 1: x -> h0
    k_agg<<<N_NODES, 128>>>(x, 0);
    k_gemm<<<GEMM_GRID, 256>>>(x, 0, 1, 0, bl[0]);
    // layer 2: h0 -> h1
    k_agg<<<N_NODES, 128>>>(x, 1);
    k_gemm<<<GEMM_GRID, 256>>>(x, 1, 2, 1, bl[1]);
    // layer 3: h1 -> h0
    k_agg<<<N_NODES, 128>>>(x, 2);
    k_gemm<<<GEMM_GRID, 256>>>(x, 2, 1, 2, bl[2]);
    // layer 4: h0 -> h1
    k_agg<<<N_NODES, 128>>>(x, 1);
    k_gemm<<<GEMM_GRID, 256>>>(x, 1, 2, 3, bl[3]);

    // readout
    k_pool<<<N_NODES, 128>>>(batch);
    k_final<<<N_GRAPHS, 128>>>(root, wcls, bcls, out);
}

// round 2
// speedup vs baseline: 1.3288x; 1.3288x over previous
#include <cuda_runtime.h>
#include <cuda_bf16.h>
#include <cstdint>

#define N_NODES  50000
#define N_EDGES  600000
#define N_GRAPHS 256
#define C        128

// ---------------- scratch (device globals; no allocations allowed) ----------
__device__ int   d_deg[N_NODES];
__device__ int   d_rowptr[N_NODES + 1];
__device__ int   d_fill[N_NODES];
__device__ int   d_esrc[N_EDGES];
__device__ float d_deginv[N_NODES];
__device__ float d_agg[N_NODES * C];
__device__ float d_h0[N_NODES * C];
__device__ float d_h1[N_NODES * C];
__device__ __nv_bfloat16 d_WTh[4][256 * 128];  // [k][co] hi split, k<128 -> W_l, k>=128 -> W_r
__device__ __nv_bfloat16 d_WTl[4][256 * 128];  // lo split
__device__ float d_gsum[N_GRAPHS * C];
__device__ float d_gcnt[N_GRAPHS];

// ---------------- helpers ----------------------------------------------------
__device__ __forceinline__ void split_bf16(float x, __nv_bfloat16& h, __nv_bfloat16& l) {
    h = __float2bfloat16(x);
    l = __float2bfloat16(x - __bfloat162float(h));
}

__device__ __forceinline__ uint32_t smem_u32(const void* p) {
    return (uint32_t)__cvta_generic_to_shared(p);
}

__device__ __forceinline__ void ldmA4(uint32_t* r, uint32_t addr) {
    asm volatile("ldmatrix.sync.aligned.m8n8.x4.shared.b16 {%0,%1,%2,%3}, [%4];"
                 : "=r"(r[0]), "=r"(r[1]), "=r"(r[2]), "=r"(r[3]) : "r"(addr));
}

__device__ __forceinline__ void ldmBT4(uint32_t* r, uint32_t addr) {
    asm volatile("ldmatrix.sync.aligned.m8n8.x4.trans.shared.b16 {%0,%1,%2,%3}, [%4];"
                 : "=r"(r[0]), "=r"(r[1]), "=r"(r[2]), "=r"(r[3]) : "r"(addr));
}

__device__ __forceinline__ void mma16816(float* c, const uint32_t* a, const uint32_t* b) {
    asm volatile(
        "mma.sync.aligned.m16n8k16.row.col.f32.bf16.bf16.f32 "
        "{%0,%1,%2,%3}, {%4,%5,%6,%7}, {%8,%9}, {%0,%1,%2,%3};"
        : "+f"(c[0]), "+f"(c[1]), "+f"(c[2]), "+f"(c[3])
        : "r"(a[0]), "r"(a[1]), "r"(a[2]), "r"(a[3]), "r"(b[0]), "r"(b[1]));
}

// ---------------- init: zero counters / accumulators ------------------------
__global__ void k_init() {
    int i = blockIdx.x * blockDim.x + threadIdx.x;
    int stride = gridDim.x * blockDim.x;
    for (int j = i; j < N_NODES; j += stride) { d_deg[j] = 0; d_fill[j] = 0; }
    for (int j = i; j < N_GRAPHS * C; j += stride) d_gsum[j] = 0.f;
    for (int j = i; j < N_GRAPHS; j += stride) d_gcnt[j] = 0.f;
}

// ---------------- degree histogram ------------------------------------------
__global__ void k_hist(const int* __restrict__ tgt) {
    int e = blockIdx.x * blockDim.x + threadIdx.x;
    if (e < N_EDGES) atomicAdd(&d_deg[tgt[e]], 1);
}

// ---------------- exclusive scan (single block, 1024 threads) ---------------
__global__ void k_scan() {
    __shared__ int sums[1024];
    const int CH = (N_NODES + 1023) / 1024;   // 49
    int t = threadIdx.x;
    int base = t * CH;
    int s = 0;
    for (int i = base; i < base + CH && i < N_NODES; i++) s += d_deg[i];
    sums[t] = s;
    __syncthreads();
    for (int off = 1; off < 1024; off <<= 1) {
        int v = 0;
        if (t >= off) v = sums[t - off];
        __syncthreads();
        if (t >= off) sums[t] += v;
        __syncthreads();
    }
    int run = (t > 0) ? sums[t - 1] : 0;
    for (int i = base; i < base + CH && i < N_NODES; i++) {
        d_rowptr[i] = run;
        int dg = d_deg[i];
        d_deginv[i] = 1.0f / (float)max(dg, 1);
        run += dg;
    }
    if (N_NODES >= base && N_NODES < base + CH) d_rowptr[N_NODES] = run;
}

// ---------------- counting-sort edges by target (CSR fill) ------------------
__global__ void k_fill(const int* __restrict__ src, const int* __restrict__ tgt) {
    int e = blockIdx.x * blockDim.x + threadIdx.x;
    if (e < N_EDGES) {
        int t = tgt[e];
        int slot = atomicAdd(&d_fill[t], 1);
        d_esrc[d_rowptr[t] + slot] = src[e];
    }
}

// ---------------- weight transpose + bf16 split: [256][128] k-major ---------
__global__ void k_wtrans(const float* __restrict__ wl, const float* __restrict__ wr, int layer) {
    int k = blockIdx.x;          // 0..255
    int co = threadIdx.x;        // 0..127
    float v = (k < 128) ? wl[co * 128 + k] : wr[co * 128 + (k - 128)];
    __nv_bfloat16 h, l;
    split_bf16(v, h, l);
    d_WTh[layer][k * 128 + co] = h;
    d_WTl[layer][k * 128 + co] = l;
}

// ---------------- mean aggregation via CSR ----------------------------------
__global__ void k_agg(const float* __restrict__ xext, int insel) {
    const float* xin = (insel == 0) ? xext : ((insel == 1) ? d_h0 : d_h1);
    int n = blockIdx.x;
    int c = threadIdx.x;
    int s0 = d_rowptr[n], s1 = d_rowptr[n + 1];
    float acc = 0.f;
    #pragma unroll 4
    for (int e = s0; e < s1; e++) {
        acc += __ldg(&xin[d_esrc[e] * C + c]);
    }
    d_agg[n * C + c] = acc * d_deginv[n];
}

// ---------------- fused SAGE linear via bf16 split-precision tensor MMA -----
// out = relu([agg | x] @ WT + b), A 128x256 per block, full N=128 output width
#define BM 128
#define BK 32
#define APAD 8
#define WPAD 8

__global__ __launch_bounds__(256) void k_gemm(
    const float* __restrict__ xext, int insel, int outsel, int layer,
    const float* __restrict__ bias)
{
    const float* Ax = (insel == 0) ? xext : ((insel == 1) ? d_h0 : d_h1);
    float* out = (outsel == 1) ? d_h0 : d_h1;
    const __nv_bfloat16* WTh = d_WTh[layer];
    const __nv_bfloat16* WTl = d_WTl[layer];

    __shared__ __nv_bfloat16 Ah[BM][BK + APAD];
    __shared__ __nv_bfloat16 Al[BM][BK + APAD];
    __shared__ __nv_bfloat16 Wh[BK][128 + WPAD];
    __shared__ __nv_bfloat16 Wl[BK][128 + WPAD];

    int tid  = threadIdx.x;
    int lane = tid & 31;
    int wid  = tid >> 5;
    int warp_m = wid & 3;     // 4 warps over M (32 rows each)
    int warp_n = wid >> 2;    // 2 warps over N (64 cols each)
    int rowBase = blockIdx.x * BM;

    float acc[2][8][4];
    #pragma unroll
    for (int mi = 0; mi < 2; mi++)
        #pragma unroll
        for (int ni = 0; ni < 8; ni++)
            #pragma unroll
            for (int q = 0; q < 4; q++) acc[mi][ni][q] = 0.f;

    // ldmatrix source addresses (constant across k-loop except kk offset)
    int a_row = warp_m * 32 + (lane & 15);
    int a_col = (lane >> 4) * 8;
    int b_row = (lane & 15);
    int b_col = warp_n * 64 + (lane >> 4) * 8;

    for (int k0 = 0; k0 < 256; k0 += BK) {
        const float* Asrc = (k0 < 128) ? d_agg : Ax;
        int kloc = k0 & 127;

        // ---- stage A: 128 rows x 32 k fp32 -> hi/lo bf16 -------------------
        {
            int r  = tid >> 1;             // 128 rows, 2 threads per row
            int ks = (tid & 1) * 16;       // 16 floats per thread
            int grow = rowBase + r;
            __nv_bfloat162* ah2 = (__nv_bfloat162*)&Ah[r][ks];
            __nv_bfloat162* al2 = (__nv_bfloat162*)&Al[r][ks];
            #pragma unroll
            for (int q = 0; q < 4; q++) {
                float4 v = make_float4(0.f, 0.f, 0.f, 0.f);
                if (grow < N_NODES)
                    v = *(const float4*)&Asrc[grow * C + kloc + ks + q * 4];
                __nv_bfloat16 h0, l0, h1, l1, h2, l2, h3, l3;
                split_bf16(v.x, h0, l0); split_bf16(v.y, h1, l1);
                split_bf16(v.z, h2, l2); split_bf16(v.w, h3, l3);
                ah2[q * 2 + 0] = __halves2bfloat162(h0, h1);
                ah2[q * 2 + 1] = __halves2bfloat162(h2, h3);
                al2[q * 2 + 0] = __halves2bfloat162(l0, l1);
                al2[q * 2 + 1] = __halves2bfloat162(l2, l3);
            }
        }
        // ---- stage W: 32 k x 128 co bf16 (hi + lo) -------------------------
        {
            int r = tid >> 3;              // 32 rows, 8 threads/row
            int c0 = (tid & 7) * 16;       // 16 bf16 per thread
            const uint4* gh = (const uint4*)&WTh[(k0 + r) * 128 + c0];
            const uint4* gl = (const uint4*)&WTl[(k0 + r) * 128 + c0];
            uint4* sh = (uint4*)&Wh[r][c0];
            uint4* sl = (uint4*)&Wl[r][c0];
            sh[0] = gh[0]; sh[1] = gh[1];
            sl[0] = gl[0]; sl[1] = gl[1];
        }
        __syncthreads();

        #pragma unroll
        for (int kk = 0; kk < 2; kk++) {
            uint32_t ah[2][4], al[2][4];
            #pragma unroll
            for (int mi = 0; mi < 2; mi++) {
                ldmA4(ah[mi], smem_u32(&Ah[a_row + mi * 16][kk * 16 + a_col]));
                ldmA4(al[mi], smem_u32(&Al[a_row + mi * 16][kk * 16 + a_col]));
            }
            uint32_t bh[8][2], bl[8][2];
            #pragma unroll
            for (int np = 0; np < 4; np++) {
                uint32_t t4[4];
                ldmBT4(t4, smem_u32(&Wh[kk * 16 + b_row][np * 16 + b_col]));
                bh[np * 2][0] = t4[0]; bh[np * 2][1] = t4[1];
                bh[np * 2 + 1][0] = t4[2]; bh[np * 2 + 1][1] = t4[3];
                ldmBT4(t4, smem_u32(&Wl[kk * 16 + b_row][np * 16 + b_col]));
                bl[np * 2][0] = t4[0]; bl[np * 2][1] = t4[1];
                bl[np * 2 + 1][0] = t4[2]; bl[np * 2 + 1][1] = t4[3];
            }
            #pragma unroll
            for (int mi = 0; mi < 2; mi++)
                #pragma unroll
                for (int ni = 0; ni < 8; ni++) {
                    mma16816(acc[mi][ni], ah[mi], bh[ni]);
                    mma16816(acc[mi][ni], ah[mi], bl[ni]);
                    mma16816(acc[mi][ni], al[mi], bh[ni]);
                }
        }
        __syncthreads();
    }

    // ---- epilogue: bias + relu + store -------------------------------------
    int orow = rowBase + warp_m * 32 + (lane >> 2);
    #pragma unroll
    for (int mi = 0; mi < 2; mi++) {
        #pragma unroll
        for (int ni = 0; ni < 8; ni++) {
            int cc = warp_n * 64 + ni * 8 + (lane & 3) * 2;
            float b0 = __ldg(&bias[cc]);
            float b1 = __ldg(&bias[cc + 1]);
            int r0 = orow + mi * 16;
            if (r0 < N_NODES) {
                float2 o;
                o.x = fmaxf(acc[mi][ni][0] + b0, 0.f);
                o.y = fmaxf(acc[mi][ni][1] + b1, 0.f);
                *(float2*)&out[r0 * C + cc] = o;
            }
            int r1 = r0 + 8;
            if (r1 < N_NODES) {
                float2 o;
                o.x = fmaxf(acc[mi][ni][2] + b0, 0.f);
                o.y = fmaxf(acc[mi][ni][3] + b1, 0.f);
                *(float2*)&out[r1 * C + cc] = o;
            }
        }
    }
}

// ---------------- graph mean pooling (sum + count via atomics) --------------
__global__ void k_pool(const int* __restrict__ batch) {
    int n = blockIdx.x;
    int c = threadIdx.x;
    int g = batch[n];
    atomicAdd(&d_gsum[g * C + c], d_h1[n * C + c]);
    if (c == 0) atomicAdd(&d_gcnt[g], 1.0f);
}

// ---------------- classifier: [root_emb | graph_mean] @ w_cls^T + b ---------
__global__ void k_final(const int* __restrict__ root,
                        const float* __restrict__ wcls,
                        const float* __restrict__ bcls,
                        float* __restrict__ out)
{
    int g = blockIdx.x;
    int c = threadIdx.x;   // 128
    float rv = d_h1[root[g] * C + c];
    float gm = d_gsum[g * C + c] / fmaxf(d_gcnt[g], 1.0f);
    __shared__ float red[2][4];
    float p0 = rv * wcls[0 * 256 + c] + gm * wcls[0 * 256 + 128 + c];
    float p1 = rv * wcls[1 * 256 + c] + gm * wcls[1 * 256 + 128 + c];
    #pragma unroll
    for (int off = 16; off > 0; off >>= 1) {
        p0 += __shfl_down_sync(0xffffffffu, p0, off);
        p1 += __shfl_down_sync(0xffffffffu, p1, off);
    }
    if ((c & 31) == 0) { red[0][c >> 5] = p0; red[1][c >> 5] = p1; }
    __syncthreads();
    if (c == 0) {
        out[g * 2 + 0] = red[0][0] + red[0][1] + red[0][2] + red[0][3] + bcls[0];
        out[g * 2 + 1] = red[1][0] + red[1][1] + red[1][2] + red[1][3] + bcls[1];
    }
}

// ---------------- launch ----------------------------------------------------
extern "C" void kernel_launch(void* const* d_in, const int* in_sizes, int n_in,
                              void* d_out, int out_size)
{
    const float* x     = (const float*)d_in[0];
    const int*   eidx  = (const int*)d_in[1];
    const int*   src   = eidx;
    const int*   tgt   = eidx + N_EDGES;
    const int*   root  = (const int*)d_in[2];
    const int*   batch = (const int*)d_in[3];
    const float* wl[4] = {(const float*)d_in[4],  (const float*)d_in[7],
                          (const float*)d_in[10], (const float*)d_in[13]};
    const float* bl[4] = {(const float*)d_in[5],  (const float*)d_in[8],
                          (const float*)d_in[11], (const float*)d_in[14]};
    const float* wr[4] = {(const float*)d_in[6],  (const float*)d_in[9],
                          (const float*)d_in[12], (const float*)d_in[15]};
    const float* wcls  = (const float*)d_in[16];
    const float* bcls  = (const float*)d_in[17];
    float* out = (float*)d_out;

    (void)in_sizes; (void)n_in; (void)out_size;

    // structure build
    k_init<<<256, 256>>>();
    k_hist<<<(N_EDGES + 255) / 256, 256>>>(tgt);
    k_scan<<<1, 1024>>>();
    k_fill<<<(N_EDGES + 255) / 256, 256>>>(src, tgt);

    // weight transposes + bf16 hi/lo split
    for (int l = 0; l < 4; l++)
        k_wtrans<<<256, 128>>>(wl[l], wr[l], l);

    const int GEMM_GRID = (N_NODES + BM - 1) / BM;   // 391

    // layer 1: x -> h0
    k_agg<<<N_NODES, 128>>>(x, 0);
    k_gemm<<<GEMM_GRID, 256>>>(x, 0, 1, 0, bl[0]);
    // layer 2: h0 -> h1
    k_agg<<<N_NODES, 128>>>(x, 1);
    k_gemm<<<GEMM_GRID, 256>>>(x, 1, 2, 1, bl[1]);
    // layer 3: h1 -> h0
    k_agg<<<N_NODES, 128>>>(x, 2);
    k_gemm<<<GEMM_GRID, 256>>>(x, 2, 1, 2, bl[2]);
    // layer 4: h0 -> h1
    k_agg<<<N_NODES, 128>>>(x, 1);
    k_gemm<<<GEMM_GRID, 256>>>(x, 1, 2, 3, bl[3]);

    // readout
    k_pool<<<N_NODES, 128>>>(batch);
    k_final<<<N_GRAPHS, 128>>>(root, wcls, bcls, out);
}

// round 4
// speedup vs baseline: 1.5516x; 1.1677x over previous
#include <cuda_runtime.h>
#include <cuda_bf16.h>
#include <cstdint>

#define N_NODES  50000
#define N_EDGES  600000
#define N_GRAPHS 256
#define C        128

// ---------------- scratch (device globals; no allocations allowed) ----------
__device__ int   d_deg[N_NODES];
__device__ int   d_rowptr[N_NODES + 1];
__device__ int   d_fill[N_NODES];
__device__ int   d_esrc[N_EDGES];
__device__ float d_deginv[N_NODES];

// activations as bf16 hi/lo pairs
__device__ __nv_bfloat16 d_xh[N_NODES * C],   d_xl[N_NODES * C];
__device__ __nv_bfloat16 d_aggh[N_NODES * C], d_aggl[N_NODES * C];
__device__ __nv_bfloat16 d_h0h[N_NODES * C],  d_h0l[N_NODES * C];
__device__ __nv_bfloat16 d_h1h[N_NODES * C],  d_h1l[N_NODES * C];

__device__ __nv_bfloat16 d_WTh[4][256 * 128];  // [k][co] hi, k<128 -> W_l, k>=128 -> W_r
__device__ __nv_bfloat16 d_WTl[4][256 * 128];  // lo
__device__ float d_gsum[N_GRAPHS * C];
__device__ float d_gcnt[N_GRAPHS];

// ---------------- helpers ----------------------------------------------------
__device__ __forceinline__ void split_bf16(float x, __nv_bfloat16& h, __nv_bfloat16& l) {
    h = __float2bfloat16(x);
    l = __float2bfloat16(x - __bfloat162float(h));
}

__device__ __forceinline__ uint32_t smem_u32(const void* p) {
    return (uint32_t)__cvta_generic_to_shared(p);
}

__device__ __forceinline__ void ldmA4(uint32_t* r, uint32_t addr) {
    asm volatile("ldmatrix.sync.aligned.m8n8.x4.shared.b16 {%0,%1,%2,%3}, [%4];"
                 : "=r"(r[0]), "=r"(r[1]), "=r"(r[2]), "=r"(r[3]) : "r"(addr));
}

__device__ __forceinline__ void ldmBT4(uint32_t* r, uint32_t addr) {
    asm volatile("ldmatrix.sync.aligned.m8n8.x4.trans.shared.b16 {%0,%1,%2,%3}, [%4];"
                 : "=r"(r[0]), "=r"(r[1]), "=r"(r[2]), "=r"(r[3]) : "r"(addr));
}

__device__ __forceinline__ void mma16816(float* c, const uint32_t* a, const uint32_t* b) {
    asm volatile(
        "mma.sync.aligned.m16n8k16.row.col.f32.bf16.bf16.f32 "
        "{%0,%1,%2,%3}, {%4,%5,%6,%7}, {%8,%9}, {%0,%1,%2,%3};"
        : "+f"(c[0]), "+f"(c[1]), "+f"(c[2]), "+f"(c[3])
        : "r"(a[0]), "r"(a[1]), "r"(a[2]), "r"(a[3]), "r"(b[0]), "r"(b[1]));
}

__device__ __forceinline__ void cpa16(uint32_t smem, const void* g, bool pred) {
    int sz = pred ? 16 : 0;
    asm volatile("cp.async.cg.shared.global [%0], [%1], 16, %2;"
                 :: "r"(smem), "l"(g), "r"(sz) : "memory");
}

// ---------------- init ------------------------------------------------------
__global__ void k_init() {
    int i = blockIdx.x * blockDim.x + threadIdx.x;
    int stride = gridDim.x * blockDim.x;
    for (int j = i; j < N_NODES; j += stride) { d_deg[j] = 0; d_fill[j] = 0; }
    for (int j = i; j < N_GRAPHS * C; j += stride) d_gsum[j] = 0.f;
    for (int j = i; j < N_GRAPHS; j += stride) d_gcnt[j] = 0.f;
}

// ---------------- degree histogram ------------------------------------------
__global__ void k_hist(const int* __restrict__ tgt) {
    int e = blockIdx.x * blockDim.x + threadIdx.x;
    if (e < N_EDGES) atomicAdd(&d_deg[tgt[e]], 1);
}

// ---------------- exclusive scan --------------------------------------------
__global__ void k_scan() {
    __shared__ int sums[1024];
    const int CH = (N_NODES + 1023) / 1024;
    int t = threadIdx.x;
    int base = t * CH;
    int s = 0;
    for (int i = base; i < base + CH && i < N_NODES; i++) s += d_deg[i];
    sums[t] = s;
    __syncthreads();
    for (int off = 1; off < 1024; off <<= 1) {
        int v = 0;
        if (t >= off) v = sums[t - off];
        __syncthreads();
        if (t >= off) sums[t] += v;
        __syncthreads();
    }
    int run = (t > 0) ? sums[t - 1] : 0;
    for (int i = base; i < base + CH && i < N_NODES; i++) {
        d_rowptr[i] = run;
        int dg = d_deg[i];
        d_deginv[i] = 1.0f / (float)max(dg, 1);
        run += dg;
    }
    if (N_NODES >= base && N_NODES < base + CH) d_rowptr[N_NODES] = run;
}

// ---------------- CSR fill ---------------------------------------------------
__global__ void k_fill(const int* __restrict__ src, const int* __restrict__ tgt) {
    int e = blockIdx.x * blockDim.x + threadIdx.x;
    if (e < N_EDGES) {
        int t = tgt[e];
        int slot = atomicAdd(&d_fill[t], 1);
        d_esrc[d_rowptr[t] + slot] = src[e];
    }
}

// ---------------- weight transpose + bf16 split ------------------------------
__global__ void k_wtrans(const float* __restrict__ wl, const float* __restrict__ wr, int layer) {
    int k = blockIdx.x;
    int co = threadIdx.x;
    float v = (k < 128) ? wl[co * 128 + k] : wr[co * 128 + (k - 128)];
    __nv_bfloat16 h, l;
    split_bf16(v, h, l);
    d_WTh[layer][k * 128 + co] = h;
    d_WTl[layer][k * 128 + co] = l;
}

// ---------------- x -> bf16 hi/lo split --------------------------------------
__global__ void k_xsplit(const float* __restrict__ x) {
    int i = blockIdx.x * blockDim.x + threadIdx.x;
    int stride = gridDim.x * blockDim.x;
    for (int j = i; j < N_NODES * C; j += stride) {
        __nv_bfloat16 h, l;
        split_bf16(x[j], h, l);
        d_xh[j] = h; d_xl[j] = l;
    }
}

// ---------------- mean aggregation via CSR (bf16 hi/lo in & out) -------------
// 128 threads, 2 nodes per block, thread handles a channel pair
__global__ void k_agg(int insel) {
    const __nv_bfloat16 *xh, *xl;
    if (insel == 0)      { xh = d_xh;  xl = d_xl;  }
    else if (insel == 1) { xh = d_h0h; xl = d_h0l; }
    else                 { xh = d_h1h; xl = d_h1l; }

    int n = blockIdx.x * 2 + (threadIdx.x >> 6);
    int c = (threadIdx.x & 63) * 2;
    if (n >= N_NODES) return;
    int s0 = d_rowptr[n], s1 = d_rowptr[n + 1];
    float ax = 0.f, ay = 0.f;
    #pragma unroll 4
    for (int e = s0; e < s1; e++) {
        int s = __ldg(&d_esrc[e]);
        __nv_bfloat162 vh = *(const __nv_bfloat162*)&xh[(size_t)s * C + c];
        __nv_bfloat162 vl = *(const __nv_bfloat162*)&xl[(size_t)s * C + c];
        ax += __bfloat162float(vh.x) + __bfloat162float(vl.x);
        ay += __bfloat162float(vh.y) + __bfloat162float(vl.y);
    }
    float di = d_deginv[n];
    ax *= di; ay *= di;
    __nv_bfloat16 hx, lx, hy, ly;
    split_bf16(ax, hx, lx);
    split_bf16(ay, hy, ly);
    *(__nv_bfloat162*)&d_aggh[(size_t)n * C + c] = __halves2bfloat162(hx, hy);
    *(__nv_bfloat162*)&d_aggl[(size_t)n * C + c] = __halves2bfloat162(lx, ly);
}

// ---------------- fused SAGE linear: bf16 split-precision MMA, cp.async -----
#define BM 128
#define BK 32
#define ASTR 40     // BK + 8 pad (bf16 units)
#define WSTR 136    // 128 + 8 pad

// dynamic smem layout (element offsets)
#define OFF_AH(buf) ((buf) * (BM * ASTR))
#define OFF_AL(buf) (2 * BM * ASTR + (buf) * (BM * ASTR))
#define OFF_WH(buf) (4 * BM * ASTR + (buf) * (BK * WSTR))
#define OFF_WL(buf) (4 * BM * ASTR + 2 * BK * WSTR + (buf) * (BK * WSTR))
#define SMEM_ELEMS  (4 * BM * ASTR + 4 * BK * WSTR)   // 37888 el = 75776 B

__global__ __launch_bounds__(256, 2) void k_gemm(
    int insel, int outsel, int layer, const float* __restrict__ bias)
{
    const __nv_bfloat16 *Axh, *Axl;
    if (insel == 0)      { Axh = d_xh;  Axl = d_xl;  }
    else if (insel == 1) { Axh = d_h0h; Axl = d_h0l; }
    else                 { Axh = d_h1h; Axl = d_h1l; }
    __nv_bfloat16 *outh = (outsel == 1) ? d_h0h : d_h1h;
    __nv_bfloat16 *outl = (outsel == 1) ? d_h0l : d_h1l;
    const __nv_bfloat16* WTh = d_WTh[layer];
    const __nv_bfloat16* WTl = d_WTl[layer];

    extern __shared__ __nv_bfloat16 sm[];

    int tid  = threadIdx.x;
    int lane = tid & 31;
    int wid  = tid >> 5;
    int warp_m = wid & 3;
    int warp_n = wid >> 2;
    int rowBase = blockIdx.x * BM;

    float acc[2][8][4];
    #pragma unroll
    for (int mi = 0; mi < 2; mi++)
        #pragma unroll
        for (int ni = 0; ni < 8; ni++)
            #pragma unroll
            for (int q = 0; q < 4; q++) acc[mi][ni][q] = 0.f;

    int a_row = warp_m * 32 + (lane & 15);
    int a_col = (lane >> 4) * 8;
    int b_row = (lane & 15);
    int b_col = warp_n * 64 + (lane >> 4) * 8;

    // ---- staging helper: cp.async one k-chunk into buffer ------------------
    auto stage = [&](int it, int buf) {
        int k0 = it * BK;
        const __nv_bfloat16 *Agh, *Agl;
        int kloc;
        if (k0 < 128) { Agh = d_aggh; Agl = d_aggl; kloc = k0; }
        else          { Agh = Axh;    Agl = Axl;    kloc = k0 - 128; }
        #pragma unroll
        for (int q = 0; q < 2; q++) {
            int ch = tid + q * 256;            // 512 chunks: A rows
            int r = ch >> 2;
            int col = (ch & 3) * 8;
            int grow = rowBase + r;
            bool ok = grow < N_NODES;
            const __nv_bfloat16* gh = &Agh[(size_t)grow * C + kloc + col];
            const __nv_bfloat16* gl = &Agl[(size_t)grow * C + kloc + col];
            cpa16(smem_u32(&sm[OFF_AH(buf) + r * ASTR + col]), gh, ok);
            cpa16(smem_u32(&sm[OFF_AL(buf) + r * ASTR + col]), gl, ok);
        }
        #pragma unroll
        for (int q = 0; q < 2; q++) {
            int ch = tid + q * 256;            // 512 chunks: W
            int r = ch >> 4;
            int co = (ch & 15) * 8;
            cpa16(smem_u32(&sm[OFF_WH(buf) + r * WSTR + co]), &WTh[(k0 + r) * 128 + co], true);
            cpa16(smem_u32(&sm[OFF_WL(buf) + r * WSTR + co]), &WTl[(k0 + r) * 128 + co], true);
        }
        asm volatile("cp.async.commit_group;" ::: "memory");
    };

    stage(0, 0);

    for (int it = 0; it < 8; it++) {
        int buf = it & 1;
        asm volatile("cp.async.wait_group 0;" ::: "memory");
        __syncthreads();
        if (it + 1 < 8) stage(it + 1, buf ^ 1);

        const __nv_bfloat16* Ah = &sm[OFF_AH(buf)];
        const __nv_bfloat16* Al = &sm[OFF_AL(buf)];
        const __nv_bfloat16* Wh = &sm[OFF_WH(buf)];
        const __nv_bfloat16* Wl = &sm[OFF_WL(buf)];

        #pragma unroll
        for (int kk = 0; kk < 2; kk++) {
            uint32_t ah[2][4], al[2][4];
            #pragma unroll
            for (int mi = 0; mi < 2; mi++) {
                ldmA4(ah[mi], smem_u32(&Ah[(a_row + mi * 16) * ASTR + kk * 16 + a_col]));
                ldmA4(al[mi], smem_u32(&Al[(a_row + mi * 16) * ASTR + kk * 16 + a_col]));
            }
            uint32_t bh[8][2], bl[8][2];
            #pragma unroll
            for (int np = 0; np < 4; np++) {
                uint32_t t4[4];
                ldmBT4(t4, smem_u32(&Wh[(kk * 16 + b_row) * WSTR + np * 16 + b_col]));
                bh[np * 2][0] = t4[0]; bh[np * 2][1] = t4[1];
                bh[np * 2 + 1][0] = t4[2]; bh[np * 2 + 1][1] = t4[3];
                ldmBT4(t4, smem_u32(&Wl[(kk * 16 + b_row) * WSTR + np * 16 + b_col]));
                bl[np * 2][0] = t4[0]; bl[np * 2][1] = t4[1];
                bl[np * 2 + 1][0] = t4[2]; bl[np * 2 + 1][1] = t4[3];
            }
            #pragma unroll
            for (int mi = 0; mi < 2; mi++)
                #pragma unroll
                for (int ni = 0; ni < 8; ni++) {
                    mma16816(acc[mi][ni], ah[mi], bh[ni]);
                    mma16816(acc[mi][ni], ah[mi], bl[ni]);
                    mma16816(acc[mi][ni], al[mi], bh[ni]);
                }
        }
        __syncthreads();
    }

    // ---- epilogue: bias + relu + split + store ------------------------------
    int orow = rowBase + warp_m * 32 + (lane >> 2);
    #pragma unroll
    for (int mi = 0; mi < 2; mi++) {
        #pragma unroll
        for (int ni = 0; ni < 8; ni++) {
            int cc = warp_n * 64 + ni * 8 + (lane & 3) * 2;
            float b0 = __ldg(&bias[cc]);
            float b1 = __ldg(&bias[cc + 1]);
            int r0 = orow + mi * 16;
            if (r0 < N_NODES) {
                float vx = fmaxf(acc[mi][ni][0] + b0, 0.f);
                float vy = fmaxf(acc[mi][ni][1] + b1, 0.f);
                __nv_bfloat16 hx, lx, hy, ly;
                split_bf16(vx, hx, lx); split_bf16(vy, hy, ly);
                *(__nv_bfloat162*)&outh[(size_t)r0 * C + cc] = __halves2bfloat162(hx, hy);
                *(__nv_bfloat162*)&outl[(size_t)r0 * C + cc] = __halves2bfloat162(lx, ly);
            }
            int r1 = r0 + 8;
            if (r1 < N_NODES) {
                float vx = fmaxf(acc[mi][ni][2] + b0, 0.f);
                float vy = fmaxf(acc[mi][ni][3] + b1, 0.f);
                __nv_bfloat16 hx, lx, hy, ly;
                split_bf16(vx, hx, lx); split_bf16(vy, hy, ly);
                *(__nv_bfloat162*)&outh[(size_t)r1 * C + cc] = __halves2bfloat162(hx, hy);
                *(__nv_bfloat162*)&outl[(size_t)r1 * C + cc] = __halves2bfloat162(lx, ly);
            }
        }
    }
}

// ---------------- graph mean pooling -----------------------------------------
__global__ void k_pool(const int* __restrict__ batch) {
    int n = blockIdx.x;
    int c = threadIdx.x;
    int g = batch[n];
    float v = __bfloat162float(d_h1h[(size_t)n * C + c]) +
              __bfloat162float(d_h1l[(size_t)n * C + c]);
    atomicAdd(&d_gsum[g * C + c], v);
    if (c == 0) atomicAdd(&d_gcnt[g], 1.0f);
}

// ---------------- classifier --------------------------------------------------
__global__ void k_final(const int* __restrict__ root,
                        const float* __restrict__ wcls,
                        const float* __restrict__ bcls,
                        float* __restrict__ out)
{
    int g = blockIdx.x;
    int c = threadIdx.x;
    int rn = root[g];
    float rv = __bfloat162float(d_h1h[(size_t)rn * C + c]) +
               __bfloat162float(d_h1l[(size_t)rn * C + c]);
    float gm = d_gsum[g * C + c] / fmaxf(d_gcnt[g], 1.0f);
    __shared__ float red[2][4];
    float p0 = rv * wcls[0 * 256 + c] + gm * wcls[0 * 256 + 128 + c];
    float p1 = rv * wcls[1 * 256 + c] + gm * wcls[1 * 256 + 128 + c];
    #pragma unroll
    for (int off = 16; off > 0; off >>= 1) {
        p0 += __shfl_down_sync(0xffffffffu, p0, off);
        p1 += __shfl_down_sync(0xffffffffu, p1, off);
    }
    if ((c & 31) == 0) { red[0][c >> 5] = p0; red[1][c >> 5] = p1; }
    __syncthreads();
    if (c == 0) {
        out[g * 2 + 0] = red[0][0] + red[0][1] + red[0][2] + red[0][3] + bcls[0];
        out[g * 2 + 1] = red[1][0] + red[1][1] + red[1][2] + red[1][3] + bcls[1];
    }
}

// ---------------- launch ------------------------------------------------------
extern "C" void kernel_launch(void* const* d_in, const int* in_sizes, int n_in,
                              void* d_out, int out_size)
{
    const float* x     = (const float*)d_in[0];
    const int*   eidx  = (const int*)d_in[1];
    const int*   src   = eidx;
    const int*   tgt   = eidx + N_EDGES;
    const int*   root  = (const int*)d_in[2];
    const int*   batch = (const int*)d_in[3];
    const float* wl[4] = {(const float*)d_in[4],  (const float*)d_in[7],
                          (const float*)d_in[10], (const float*)d_in[13]};
    const float* bl[4] = {(const float*)d_in[5],  (const float*)d_in[8],
                          (const float*)d_in[11], (const float*)d_in[14]};
    const float* wr[4] = {(const float*)d_in[6],  (const float*)d_in[9],
                          (const float*)d_in[12], (const float*)d_in[15]};
    const float* wcls  = (const float*)d_in[16];
    const float* bcls  = (const float*)d_in[17];
    float* out = (float*)d_out;

    (void)in_sizes; (void)n_in; (void)out_size;

    static bool attr_set = false;
    if (!attr_set) {
        cudaFuncSetAttribute(k_gemm, cudaFuncAttributeMaxDynamicSharedMemorySize,
                             SMEM_ELEMS * (int)sizeof(__nv_bfloat16));
        attr_set = true;
    }

    // structure build
    k_init<<<256, 256>>>();
    k_hist<<<(N_EDGES + 255) / 256, 256>>>(tgt);
    k_scan<<<1, 1024>>>();
    k_fill<<<(N_EDGES + 255) / 256, 256>>>(src, tgt);

    // weight + input prep
    for (int l = 0; l < 4; l++)
        k_wtrans<<<256, 128>>>(wl[l], wr[l], l);
    k_xsplit<<<256, 256>>>(x);

    const int GEMM_GRID = (N_NODES + BM - 1) / BM;   // 391
    const int AGG_GRID  = (N_NODES + 1) / 2;         // 25000
    const int SMEM_B    = SMEM_ELEMS * (int)sizeof(__nv_bfloat16);

    // layer 1: x -> h0
    k_agg<<<AGG_GRID, 128>>>(0);
    k_gemm<<<GEMM_GRID, 256, SMEM_B>>>(0, 1, 0, bl[0]);
    // layer 2: h0 -> h1
    k_agg<<<AGG_GRID, 128>>>(1);
    k_gemm<<<GEMM_GRID, 256, SMEM_B>>>(1, 2, 1, bl[1]);
    // layer 3: h1 -> h0
    k_agg<<<AGG_GRID, 128>>>(2);
    k_gemm<<<GEMM_GRID, 256, SMEM_B>>>(2, 1, 2, bl[2]);
    // layer 4: h0 -> h1
    k_agg<<<AGG_GRID, 128>>>(1);
    k_gemm<<<GEMM_GRID, 256, SMEM_B>>>(1, 2, 3, bl[3]);

    // readout
    k_pool<<<N_NODES, 128>>>(batch);
    k_final<<<N_GRAPHS, 128>>>(root, wcls, bcls, out);
}

// round 10
// speedup vs baseline: 1.6651x; 1.0731x over previous
#include <cuda_runtime.h>
#include <cuda_bf16.h>
#include <cstdint>

#define N_NODES  50000
#define N_EDGES  600000
#define N_GRAPHS 256
#define C        128

// ---------------- scratch (device globals; no allocations allowed) ----------
__device__ int   d_deg[N_NODES];
__device__ int   d_rowptr[N_NODES + 1];
__device__ int   d_fill[N_NODES];
__device__ int   d_esrc[N_EDGES];
__device__ float d_deginv[N_NODES];

// activations as bf16 hi/lo pairs
__device__ __nv_bfloat16 d_xh[N_NODES * C],   d_xl[N_NODES * C];
__device__ __nv_bfloat16 d_aggh[N_NODES * C], d_aggl[N_NODES * C];
__device__ __nv_bfloat16 d_h0h[N_NODES * C],  d_h0l[N_NODES * C];
__device__ __nv_bfloat16 d_h1h[N_NODES * C],  d_h1l[N_NODES * C];

// weights: [k][co] K-major concat (k<128 -> W_l, k>=128 -> W_r)
__device__ __nv_bfloat16 d_WTh[4][256 * 128];
__device__ __nv_bfloat16 d_WTl[4][256 * 128];
__device__ float d_gsum[N_GRAPHS * C];
__device__ float d_gcnt[N_GRAPHS];

// ---------------- helpers ----------------------------------------------------
__device__ __forceinline__ void split_bf16(float x, __nv_bfloat16& h, __nv_bfloat16& l) {
    h = __float2bfloat16(x);
    l = __float2bfloat16(x - __bfloat162float(h));
}

__device__ __forceinline__ uint32_t smem_u32(const void* p) {
    return (uint32_t)__cvta_generic_to_shared(p);
}

__device__ __forceinline__ void ldmA4(uint32_t* r, uint32_t addr) {
    asm volatile("ldmatrix.sync.aligned.m8n8.x4.shared.b16 {%0,%1,%2,%3}, [%4];"
                 : "=r"(r[0]), "=r"(r[1]), "=r"(r[2]), "=r"(r[3]) : "r"(addr));
}

__device__ __forceinline__ void ldmBT4(uint32_t* r, uint32_t addr) {
    asm volatile("ldmatrix.sync.aligned.m8n8.x4.trans.shared.b16 {%0,%1,%2,%3}, [%4];"
                 : "=r"(r[0]), "=r"(r[1]), "=r"(r[2]), "=r"(r[3]) : "r"(addr));
}

__device__ __forceinline__ void mma16816(float* c, const uint32_t* a, const uint32_t* b) {
    asm volatile(
        "mma.sync.aligned.m16n8k16.row.col.f32.bf16.bf16.f32 "
        "{%0,%1,%2,%3}, {%4,%5,%6,%7}, {%8,%9}, {%0,%1,%2,%3};"
        : "+f"(c[0]), "+f"(c[1]), "+f"(c[2]), "+f"(c[3])
        : "r"(a[0]), "r"(a[1]), "r"(a[2]), "r"(a[3]), "r"(b[0]), "r"(b[1]));
}

__device__ __forceinline__ void cpa16(uint32_t smem, const void* g, bool pred) {
    int sz = pred ? 16 : 0;
    asm volatile("cp.async.cg.shared.global [%0], [%1], 16, %2;"
                 :: "r"(smem), "l"(g), "r"(sz) : "memory");
}

// ---------------- fused preprocessing: hist + xsplit + wsplit ----------------
#define HB 2344
#define XB 1024
#define WB 512
__global__ void k_prep(const int* __restrict__ tgt, const float* __restrict__ x,
                       const float* __restrict__ wl0, const float* __restrict__ wr0,
                       const float* __restrict__ wl1, const float* __restrict__ wr1,
                       const float* __restrict__ wl2, const float* __restrict__ wr2,
                       const float* __restrict__ wl3, const float* __restrict__ wr3)
{
    int bid = blockIdx.x;
    int tid = threadIdx.x;
    if (bid < HB) {
        int e = bid * 256 + tid;
        if (e < N_EDGES) atomicAdd(&d_deg[tgt[e]], 1);
    } else if (bid < HB + XB) {
        int gid = (bid - HB) * 256 + tid;
        for (int j = gid; j < N_NODES * C; j += XB * 256) {
            __nv_bfloat16 h, l;
            split_bf16(x[j], h, l);
            d_xh[j] = h; d_xl[j] = l;
        }
    } else {
        int idx = (bid - HB - XB) * 256 + tid;   // < 4*256*128
        int layer = idx >> 15;
        int rem = idx & 32767;
        int k  = rem >> 7;     // 0..255
        int co = rem & 127;    // 0..127
        const float* wl = (layer == 0) ? wl0 : (layer == 1) ? wl1 : (layer == 2) ? wl2 : wl3;
        const float* wr = (layer == 0) ? wr0 : (layer == 1) ? wr1 : (layer == 2) ? wr2 : wr3;
        float v = (k < 128) ? wl[co * 128 + k] : wr[co * 128 + (k - 128)];
        __nv_bfloat16 h, l;
        split_bf16(v, h, l);
        d_WTh[layer][k * 128 + co] = h;
        d_WTl[layer][k * 128 + co] = l;
    }
}

// ---------------- exclusive scan --------------------------------------------
__global__ void k_scan() {
    __shared__ int sums[1024];
    const int CH = (N_NODES + 1023) / 1024;
    int t = threadIdx.x;
    int base = t * CH;
    int s = 0;
    for (int i = base; i < base + CH && i < N_NODES; i++) s += d_deg[i];
    sums[t] = s;
    __syncthreads();
    for (int off = 1; off < 1024; off <<= 1) {
        int v = 0;
        if (t >= off) v = sums[t - off];
        __syncthreads();
        if (t >= off) sums[t] += v;
        __syncthreads();
    }
    int run = (t > 0) ? sums[t - 1] : 0;
    for (int i = base; i < base + CH && i < N_NODES; i++) {
        d_rowptr[i] = run;
        int dg = d_deg[i];
        d_deginv[i] = 1.0f / (float)max(dg, 1);
        run += dg;
    }
    if (N_NODES >= base && N_NODES < base + CH) d_rowptr[N_NODES] = run;
}

// ---------------- CSR fill ---------------------------------------------------
__global__ void k_fill(const int* __restrict__ src, const int* __restrict__ tgt) {
    int e = blockIdx.x * blockDim.x + threadIdx.x;
    if (e < N_EDGES) {
        int t = tgt[e];
        int slot = atomicAdd(&d_fill[t], 1);
        d_esrc[d_rowptr[t] + slot] = src[e];
    }
}

// ---------------- mean aggregation: warp per node ----------------------------
__global__ __launch_bounds__(256) void k_agg(int insel) {
    const __nv_bfloat16 *xh, *xl;
    if (insel == 0)      { xh = d_xh;  xl = d_xl;  }
    else if (insel == 1) { xh = d_h0h; xl = d_h0l; }
    else                 { xh = d_h1h; xl = d_h1l; }

    int wid  = threadIdx.x >> 5;
    int lane = threadIdx.x & 31;
    int n = blockIdx.x * 8 + wid;
    if (n >= N_NODES) return;
    int ch = lane * 4;
    int s0 = d_rowptr[n], s1 = d_rowptr[n + 1];
    float a0 = 0.f, a1 = 0.f, a2 = 0.f, a3 = 0.f;
    #pragma unroll 2
    for (int e = s0; e < s1; e++) {
        int s = __ldg(&d_esrc[e]);
        uint2 vh = *(const uint2*)&xh[(size_t)s * C + ch];
        uint2 vl = *(const uint2*)&xl[(size_t)s * C + ch];
        float2 h01 = __bfloat1622float2(*reinterpret_cast<__nv_bfloat162*>(&vh.x));
        float2 h23 = __bfloat1622float2(*reinterpret_cast<__nv_bfloat162*>(&vh.y));
        float2 l01 = __bfloat1622float2(*reinterpret_cast<__nv_bfloat162*>(&vl.x));
        float2 l23 = __bfloat1622float2(*reinterpret_cast<__nv_bfloat162*>(&vl.y));
        a0 += h01.x + l01.x;
        a1 += h01.y + l01.y;
        a2 += h23.x + l23.x;
        a3 += h23.y + l23.y;
    }
    float di = d_deginv[n];
    a0 *= di; a1 *= di; a2 *= di; a3 *= di;
    __nv_bfloat16 h0, l0, h1, l1, h2, l2, h3, l3;
    split_bf16(a0, h0, l0); split_bf16(a1, h1, l1);
    split_bf16(a2, h2, l2); split_bf16(a3, h3, l3);
    uint2 oh, ol;
    __nv_bfloat162 t;
    t = __halves2bfloat162(h0, h1); oh.x = *reinterpret_cast<uint32_t*>(&t);
    t = __halves2bfloat162(h2, h3); oh.y = *reinterpret_cast<uint32_t*>(&t);
    t = __halves2bfloat162(l0, l1); ol.x = *reinterpret_cast<uint32_t*>(&t);
    t = __halves2bfloat162(l2, l3); ol.y = *reinterpret_cast<uint32_t*>(&t);
    *(uint2*)&d_aggh[(size_t)n * C + ch] = oh;
    *(uint2*)&d_aggl[(size_t)n * C + ch] = ol;
}

// ---------------- SAGE linear: bf16 split-precision mma.sync, 4-stage pipe ---
// Per CTA: D[128,128] = [agg|x](128x256) @ W^T, 3-term split.
// BK=16, 16 k-iters, 4 cp.async stages, 1 __syncthreads per iter.
#define ASTR 24      // 16 + 8 pad (bf16 el)
#define WSTR 136     // 128 + 8 pad
#define A_EL (128 * ASTR)          // 3072
#define W_EL (16 * WSTR)           // 2176
#define STAGE_EL (2 * A_EL + 2 * W_EL)   // 10496
#define OFF_AH(s) ((s) * STAGE_EL)
#define OFF_AL(s) ((s) * STAGE_EL + A_EL)
#define OFF_WH(s) ((s) * STAGE_EL + 2 * A_EL)
#define OFF_WL(s) ((s) * STAGE_EL + 2 * A_EL + W_EL)
#define GEMM_SMEM_B (4 * STAGE_EL * 2)   // 83968 bytes

__global__ __launch_bounds__(256, 2) void k_gemm(
    int insel, int outsel, int layer, const float* __restrict__ bias)
{
    const __nv_bfloat16 *Xh_, *Xl_;
    if (insel == 0)      { Xh_ = d_xh;  Xl_ = d_xl;  }
    else if (insel == 1) { Xh_ = d_h0h; Xl_ = d_h0l; }
    else                 { Xh_ = d_h1h; Xl_ = d_h1l; }
    __nv_bfloat16* outh = (outsel == 1) ? d_h0h : d_h1h;
    __nv_bfloat16* outl = (outsel == 1) ? d_h0l : d_h1l;
    const __nv_bfloat16* WTh = d_WTh[layer];
    const __nv_bfloat16* WTl = d_WTl[layer];

    extern __shared__ __align__(16) __nv_bfloat16 sm[];

    int tid  = threadIdx.x;
    int lane = tid & 31;
    int wid  = tid >> 5;
    int warp_m = wid & 3;     // 4 warps over M (32 rows each)
    int warp_n = wid >> 2;    // 2 warps over N (64 cols each)
    int rowBase = blockIdx.x * 128;

    float acc[2][8][4];
    #pragma unroll
    for (int mi = 0; mi < 2; mi++)
        #pragma unroll
        for (int ni = 0; ni < 8; ni++)
            #pragma unroll
            for (int q = 0; q < 4; q++) acc[mi][ni][q] = 0.f;

    int a_row = warp_m * 32 + (lane & 15);
    int a_col = (lane >> 4) * 8;
    int b_row = (lane & 15);
    int b_col = warp_n * 64 + (lane >> 4) * 8;

    // ---- stage one 16-k chunk into stage buffer (it & 3) --------------------
    auto stage = [&](int it) {
        int buf = it & 3;
        const __nv_bfloat16 *sAh, *sAl;
        int kloc;
        if (it < 8) { sAh = d_aggh; sAl = d_aggl; kloc = it * 16; }
        else        { sAh = Xh_;    sAl = Xl_;    kloc = (it - 8) * 16; }
        #pragma unroll
        for (int g = 0; g < 4; g++) {
            int gid = tid + g * 256;             // 0..1023
            if (gid < 512) {                      // A: 2 arrays x 128 rows x 2 chunks
                int arr = gid >> 8;
                int r   = (gid & 255) >> 1;
                int j   = gid & 1;
                int grow = rowBase + r;
                const __nv_bfloat16* s = (arr ? sAl : sAh) + (size_t)grow * C + kloc + j * 8;
                uint32_t dst = smem_u32(&sm[(arr ? OFF_AL(buf) : OFF_AH(buf)) + r * ASTR + j * 8]);
                cpa16(dst, s, grow < N_NODES);
            } else {                              // W: 2 arrays x 16 rows x 16 chunks
                int g2  = gid - 512;
                int arr = g2 >> 8;
                int r   = (g2 & 255) >> 4;
                int j   = g2 & 15;
                const __nv_bfloat16* s = (arr ? WTl : WTh) + (it * 16 + r) * 128 + j * 8;
                uint32_t dst = smem_u32(&sm[(arr ? OFF_WL(buf) : OFF_WH(buf)) + r * WSTR + j * 8]);
                cpa16(dst, s, true);
            }
        }
        asm volatile("cp.async.commit_group;" ::: "memory");
    };

    stage(0); stage(1); stage(2);

    for (int it = 0; it < 16; it++) {
        int buf = it & 3;
        if (it < 13) asm volatile("cp.async.wait_group 2;" ::: "memory");
        else         asm volatile("cp.async.wait_group 0;" ::: "memory");
        __syncthreads();
        if (it + 3 < 16) stage(it + 3);

        const __nv_bfloat16* Ah = &sm[OFF_AH(buf)];
        const __nv_bfloat16* Al = &sm[OFF_AL(buf)];
        const __nv_bfloat16* Wh = &sm[OFF_WH(buf)];
        const __nv_bfloat16* Wl = &sm[OFF_WL(buf)];

        uint32_t ah[2][4], al[2][4];
        #pragma unroll
        for (int mi = 0; mi < 2; mi++) {
            ldmA4(ah[mi], smem_u32(&Ah[(a_row + mi * 16) * ASTR + a_col]));
            ldmA4(al[mi], smem_u32(&Al[(a_row + mi * 16) * ASTR + a_col]));
        }
        uint32_t bh[8][2], bl[8][2];
        #pragma unroll
        for (int np = 0; np < 4; np++) {
            uint32_t t4[4];
            ldmBT4(t4, smem_u32(&Wh[b_row * WSTR + np * 16 + b_col]));
            bh[np * 2][0] = t4[0]; bh[np * 2][1] = t4[1];
            bh[np * 2 + 1][0] = t4[2]; bh[np * 2 + 1][1] = t4[3];
            ldmBT4(t4, smem_u32(&Wl[b_row * WSTR + np * 16 + b_col]));
            bl[np * 2][0] = t4[0]; bl[np * 2][1] = t4[1];
            bl[np * 2 + 1][0] = t4[2]; bl[np * 2 + 1][1] = t4[3];
        }
        #pragma unroll
        for (int mi = 0; mi < 2; mi++)
            #pragma unroll
            for (int ni = 0; ni < 8; ni++) {
                mma16816(acc[mi][ni], ah[mi], bh[ni]);
                mma16816(acc[mi][ni], ah[mi], bl[ni]);
                mma16816(acc[mi][ni], al[mi], bh[ni]);
            }
    }

    // ---- epilogue: bias + relu + split + store ------------------------------
    int orow = rowBase + warp_m * 32 + (lane >> 2);
    #pragma unroll
    for (int mi = 0; mi < 2; mi++) {
        #pragma unroll
        for (int ni = 0; ni < 8; ni++) {
            int cc = warp_n * 64 + ni * 8 + (lane & 3) * 2;
            float b0 = __ldg(&bias[cc]);
            float b1 = __ldg(&bias[cc + 1]);
            int r0 = orow + mi * 16;
            if (r0 < N_NODES) {
                float vx = fmaxf(acc[mi][ni][0] + b0, 0.f);
                float vy = fmaxf(acc[mi][ni][1] + b1, 0.f);
                __nv_bfloat16 hx, lx, hy, ly;
                split_bf16(vx, hx, lx); split_bf16(vy, hy, ly);
                *(__nv_bfloat162*)&outh[(size_t)r0 * C + cc] = __halves2bfloat162(hx, hy);
                *(__nv_bfloat162*)&outl[(size_t)r0 * C + cc] = __halves2bfloat162(lx, ly);
            }
            int r1 = r0 + 8;
            if (r1 < N_NODES) {
                float vx = fmaxf(acc[mi][ni][2] + b0, 0.f);
                float vy = fmaxf(acc[mi][ni][3] + b1, 0.f);
                __nv_bfloat16 hx, lx, hy, ly;
                split_bf16(vx, hx, lx); split_bf16(vy, hy, ly);
                *(__nv_bfloat162*)&outh[(size_t)r1 * C + cc] = __halves2bfloat162(hx, hy);
                *(__nv_bfloat162*)&outl[(size_t)r1 * C + cc] = __halves2bfloat162(lx, ly);
            }
        }
    }
}

// ---------------- graph mean pooling -----------------------------------------
__global__ void k_pool(const int* __restrict__ batch) {
    int n = blockIdx.x;
    int c = threadIdx.x;
    int g = batch[n];
    float v = __bfloat162float(d_h1h[(size_t)n * C + c]) +
              __bfloat162float(d_h1l[(size_t)n * C + c]);
    atomicAdd(&d_gsum[g * C + c], v);
    if (c == 0) atomicAdd(&d_gcnt[g], 1.0f);
}

// ---------------- classifier --------------------------------------------------
__global__ void k_final(const int* __restrict__ root,
                        const float* __restrict__ wcls,
                        const float* __restrict__ bcls,
                        float* __restrict__ out)
{
    int g = blockIdx.x;
    int c = threadIdx.x;
    int rn = root[g];
    float rv = __bfloat162float(d_h1h[(size_t)rn * C + c]) +
               __bfloat162float(d_h1l[(size_t)rn * C + c]);
    float gm = d_gsum[g * C + c] / fmaxf(d_gcnt[g], 1.0f);
    __shared__ float red[2][4];
    float p0 = rv * wcls[0 * 256 + c] + gm * wcls[0 * 256 + 128 + c];
    float p1 = rv * wcls[1 * 256 + c] + gm * wcls[1 * 256 + 128 + c];
    #pragma unroll
    for (int off = 16; off > 0; off >>= 1) {
        p0 += __shfl_down_sync(0xffffffffu, p0, off);
        p1 += __shfl_down_sync(0xffffffffu, p1, off);
    }
    if ((c & 31) == 0) { red[0][c >> 5] = p0; red[1][c >> 5] = p1; }
    __syncthreads();
    if (c == 0) {
        out[g * 2 + 0] = red[0][0] + red[0][1] + red[0][2] + red[0][3] + bcls[0];
        out[g * 2 + 1] = red[1][0] + red[1][1] + red[1][2] + red[1][3] + bcls[1];
    }
}

// ---------------- launch ------------------------------------------------------
extern "C" void kernel_launch(void* const* d_in, const int* in_sizes, int n_in,
                              void* d_out, int out_size)
{
    const float* x     = (const float*)d_in[0];
    const int*   eidx  = (const int*)d_in[1];
    const int*   src   = eidx;
    const int*   tgt   = eidx + N_EDGES;
    const int*   root  = (const int*)d_in[2];
    const int*   batch = (const int*)d_in[3];
    const float* wl[4] = {(const float*)d_in[4],  (const float*)d_in[7],
                          (const float*)d_in[10], (const float*)d_in[13]};
    const float* bl[4] = {(const float*)d_in[5],  (const float*)d_in[8],
                          (const float*)d_in[11], (const float*)d_in[14]};
    const float* wr[4] = {(const float*)d_in[6],  (const float*)d_in[9],
                          (const float*)d_in[12], (const float*)d_in[15]};
    const float* wcls  = (const float*)d_in[16];
    const float* bcls  = (const float*)d_in[17];
    float* out = (float*)d_out;

    (void)in_sizes; (void)n_in; (void)out_size;

    static bool attr_set = false;
    static void *p_deg = nullptr, *p_fill = nullptr, *p_gsum = nullptr, *p_gcnt = nullptr;
    if (!attr_set) {
        cudaFuncSetAttribute(k_gemm, cudaFuncAttributeMaxDynamicSharedMemorySize, GEMM_SMEM_B);
        cudaGetSymbolAddress(&p_deg,  d_deg);
        cudaGetSymbolAddress(&p_fill, d_fill);
        cudaGetSymbolAddress(&p_gsum, d_gsum);
        cudaGetSymbolAddress(&p_gcnt, d_gcnt);
        attr_set = true;
    }

    // zero counters/accumulators via memset nodes (not kernel launches)
    cudaMemsetAsync(p_deg,  0, N_NODES * sizeof(int));
    cudaMemsetAsync(p_fill, 0, N_NODES * sizeof(int));
    cudaMemsetAsync(p_gsum, 0, N_GRAPHS * C * sizeof(float));
    cudaMemsetAsync(p_gcnt, 0, N_GRAPHS * sizeof(float));

    // 1: fused preprocessing (degree hist + x split + weight split)
    k_prep<<<HB + XB + WB, 256>>>(tgt, x,
                                  wl[0], wr[0], wl[1], wr[1],
                                  wl[2], wr[2], wl[3], wr[3]);
    // 2-3: scan + CSR fill
    k_scan<<<1, 1024>>>();
    k_fill<<<(N_EDGES + 255) / 256, 256>>>(src, tgt);

    const int GEMM_GRID = (N_NODES + 127) / 128;   // 391
    const int AGG_GRID  = (N_NODES + 7) / 8;       // 6250

    // layers
    k_agg<<<AGG_GRID, 256>>>(0);
    k_gemm<<<GEMM_GRID, 256, GEMM_SMEM_B>>>(0, 1, 0, bl[0]);
    k_agg<<<AGG_GRID, 256>>>(1);
    k_gemm<<<GEMM_GRID, 256, GEMM_SMEM_B>>>(1, 2, 1, bl[1]);
    k_agg<<<AGG_GRID, 256>>>(2);
    k_gemm<<<GEMM_GRID, 256, GEMM_SMEM_B>>>(2, 1, 2, bl[2]);
    k_agg<<<AGG_GRID, 256>>>(1);
    k_gemm<<<GEMM_GRID, 256, GEMM_SMEM_B>>>(1, 2, 3, bl[3]);

    // readout
    k_pool<<<N_NODES, 128>>>(batch);
    k_final<<<N_GRAPHS, 128>>>(root, wcls, bcls, out);
}

// round 11
// speedup vs baseline: 1.7142x; 1.0295x over previous
#include <cuda_runtime.h>
#include <cuda_bf16.h>
#include <cstdint>

#define N_NODES  50000
#define N_EDGES  600000
#define N_GRAPHS 256
#define C        128

// ---------------- scratch (device globals; no allocations allowed) ----------
__device__ int   d_deg[N_NODES];
__device__ int   d_rowptr[N_NODES + 1];
__device__ int   d_fill[N_NODES];
__device__ int   d_esrc[N_EDGES];
__device__ float d_deginv[N_NODES];

// activations: bf16 hi/lo pairs (GEMM A operand) + fp32 copies (agg input)
__device__ __nv_bfloat16 d_xh[N_NODES * C],   d_xl[N_NODES * C];
__device__ __nv_bfloat16 d_aggh[N_NODES * C], d_aggl[N_NODES * C];
__device__ __nv_bfloat16 d_h0h[N_NODES * C],  d_h0l[N_NODES * C];
__device__ __nv_bfloat16 d_h1h[N_NODES * C],  d_h1l[N_NODES * C];
__device__ float d_h0f[N_NODES * C];
__device__ float d_h1f[N_NODES * C];

// weights: [k][co] K-major concat (k<128 -> W_l, k>=128 -> W_r)
__device__ __nv_bfloat16 d_WTh[4][256 * 128];
__device__ __nv_bfloat16 d_WTl[4][256 * 128];
__device__ float d_gsum[N_GRAPHS * C];
__device__ float d_gcnt[N_GRAPHS];

// ---------------- helpers ----------------------------------------------------
__device__ __forceinline__ void split_bf16(float x, __nv_bfloat16& h, __nv_bfloat16& l) {
    h = __float2bfloat16(x);
    l = __float2bfloat16(x - __bfloat162float(h));
}

__device__ __forceinline__ uint32_t smem_u32(const void* p) {
    return (uint32_t)__cvta_generic_to_shared(p);
}

__device__ __forceinline__ void ldmA4(uint32_t* r, uint32_t addr) {
    asm volatile("ldmatrix.sync.aligned.m8n8.x4.shared.b16 {%0,%1,%2,%3}, [%4];"
                 : "=r"(r[0]), "=r"(r[1]), "=r"(r[2]), "=r"(r[3]) : "r"(addr));
}

__device__ __forceinline__ void ldmBT4(uint32_t* r, uint32_t addr) {
    asm volatile("ldmatrix.sync.aligned.m8n8.x4.trans.shared.b16 {%0,%1,%2,%3}, [%4];"
                 : "=r"(r[0]), "=r"(r[1]), "=r"(r[2]), "=r"(r[3]) : "r"(addr));
}

__device__ __forceinline__ void mma16816(float* c, const uint32_t* a, const uint32_t* b) {
    asm volatile(
        "mma.sync.aligned.m16n8k16.row.col.f32.bf16.bf16.f32 "
        "{%0,%1,%2,%3}, {%4,%5,%6,%7}, {%8,%9}, {%0,%1,%2,%3};"
        : "+f"(c[0]), "+f"(c[1]), "+f"(c[2]), "+f"(c[3])
        : "r"(a[0]), "r"(a[1]), "r"(a[2]), "r"(a[3]), "r"(b[0]), "r"(b[1]));
}

__device__ __forceinline__ void cpa16(uint32_t smem, const void* g, bool pred) {
    int sz = pred ? 16 : 0;
    asm volatile("cp.async.cg.shared.global [%0], [%1], 16, %2;"
                 :: "r"(smem), "l"(g), "r"(sz) : "memory");
}

// ---------------- fused preprocessing: hist + xsplit + wsplit ----------------
#define HB 2344
#define XB 1024
#define WB 512
__global__ void k_prep(const int* __restrict__ tgt, const float* __restrict__ x,
                       const float* __restrict__ wl0, const float* __restrict__ wr0,
                       const float* __restrict__ wl1, const float* __restrict__ wr1,
                       const float* __restrict__ wl2, const float* __restrict__ wr2,
                       const float* __restrict__ wl3, const float* __restrict__ wr3)
{
    int bid = blockIdx.x;
    int tid = threadIdx.x;
    if (bid < HB) {
        int e = bid * 256 + tid;
        if (e < N_EDGES) atomicAdd(&d_deg[tgt[e]], 1);
    } else if (bid < HB + XB) {
        int gid = (bid - HB) * 256 + tid;
        for (int j = gid; j < N_NODES * C; j += XB * 256) {
            __nv_bfloat16 h, l;
            split_bf16(x[j], h, l);
            d_xh[j] = h; d_xl[j] = l;
        }
    } else {
        int idx = (bid - HB - XB) * 256 + tid;   // < 4*256*128
        int layer = idx >> 15;
        int rem = idx & 32767;
        int k  = rem >> 7;     // 0..255
        int co = rem & 127;    // 0..127
        const float* wl = (layer == 0) ? wl0 : (layer == 1) ? wl1 : (layer == 2) ? wl2 : wl3;
        const float* wr = (layer == 0) ? wr0 : (layer == 1) ? wr1 : (layer == 2) ? wr2 : wr3;
        float v = (k < 128) ? wl[co * 128 + k] : wr[co * 128 + (k - 128)];
        __nv_bfloat16 h, l;
        split_bf16(v, h, l);
        d_WTh[layer][k * 128 + co] = h;
        d_WTl[layer][k * 128 + co] = l;
    }
}

// ---------------- exclusive scan --------------------------------------------
__global__ void k_scan() {
    __shared__ int sums[1024];
    const int CH = (N_NODES + 1023) / 1024;
    int t = threadIdx.x;
    int base = t * CH;
    int s = 0;
    for (int i = base; i < base + CH && i < N_NODES; i++) s += d_deg[i];
    sums[t] = s;
    __syncthreads();
    for (int off = 1; off < 1024; off <<= 1) {
        int v = 0;
        if (t >= off) v = sums[t - off];
        __syncthreads();
        if (t >= off) sums[t] += v;
        __syncthreads();
    }
    int run = (t > 0) ? sums[t - 1] : 0;
    for (int i = base; i < base + CH && i < N_NODES; i++) {
        d_rowptr[i] = run;
        int dg = d_deg[i];
        d_deginv[i] = 1.0f / (float)max(dg, 1);
        run += dg;
    }
    if (N_NODES >= base && N_NODES < base + CH) d_rowptr[N_NODES] = run;
}

// ---------------- CSR fill ---------------------------------------------------
__global__ void k_fill(const int* __restrict__ src, const int* __restrict__ tgt) {
    int e = blockIdx.x * blockDim.x + threadIdx.x;
    if (e < N_EDGES) {
        int t = tgt[e];
        int slot = atomicAdd(&d_fill[t], 1);
        d_esrc[d_rowptr[t] + slot] = src[e];
    }
}

// ---------------- profiling-alignment no-op ----------------------------------
__global__ void k_nop() {}

// ---------------- mean aggregation: warp per node, fp32 input ----------------
__global__ __launch_bounds__(256) void k_agg(const float* __restrict__ xf, int insel) {
    const float* xin = (insel == 0) ? xf : ((insel == 1) ? d_h0f : d_h1f);

    int wid  = threadIdx.x >> 5;
    int lane = threadIdx.x & 31;
    int n = blockIdx.x * 8 + wid;
    if (n >= N_NODES) return;
    int ch = lane * 4;
    int s0 = d_rowptr[n], s1 = d_rowptr[n + 1];
    float a0 = 0.f, a1 = 0.f, a2 = 0.f, a3 = 0.f;
    #pragma unroll 2
    for (int e = s0; e < s1; e++) {
        int s = __ldg(&d_esrc[e]);
        float4 v = __ldg((const float4*)&xin[(size_t)s * C + ch]);
        a0 += v.x; a1 += v.y; a2 += v.z; a3 += v.w;
    }
    float di = d_deginv[n];
    a0 *= di; a1 *= di; a2 *= di; a3 *= di;
    __nv_bfloat16 h0, l0, h1, l1, h2, l2, h3, l3;
    split_bf16(a0, h0, l0); split_bf16(a1, h1, l1);
    split_bf16(a2, h2, l2); split_bf16(a3, h3, l3);
    uint2 oh, ol;
    __nv_bfloat162 t;
    t = __halves2bfloat162(h0, h1); oh.x = *reinterpret_cast<uint32_t*>(&t);
    t = __halves2bfloat162(h2, h3); oh.y = *reinterpret_cast<uint32_t*>(&t);
    t = __halves2bfloat162(l0, l1); ol.x = *reinterpret_cast<uint32_t*>(&t);
    t = __halves2bfloat162(l2, l3); ol.y = *reinterpret_cast<uint32_t*>(&t);
    *(uint2*)&d_aggh[(size_t)n * C + ch] = oh;
    *(uint2*)&d_aggl[(size_t)n * C + ch] = ol;
}

// ---------------- SAGE linear: bf16 split-precision mma.sync, 4-stage pipe ---
#define ASTR 24      // 16 + 8 pad (bf16 el)
#define WSTR 136     // 128 + 8 pad
#define A_EL (128 * ASTR)
#define W_EL (16 * WSTR)
#define STAGE_EL (2 * A_EL + 2 * W_EL)
#define OFF_AH(s) ((s) * STAGE_EL)
#define OFF_AL(s) ((s) * STAGE_EL + A_EL)
#define OFF_WH(s) ((s) * STAGE_EL + 2 * A_EL)
#define OFF_WL(s) ((s) * STAGE_EL + 2 * A_EL + W_EL)
#define GEMM_SMEM_B (4 * STAGE_EL * 2)   // 83968 bytes

__global__ __launch_bounds__(256, 2) void k_gemm(
    int insel, int outsel, int layer, const float* __restrict__ bias)
{
    const __nv_bfloat16 *Xh_, *Xl_;
    if (insel == 0)      { Xh_ = d_xh;  Xl_ = d_xl;  }
    else if (insel == 1) { Xh_ = d_h0h; Xl_ = d_h0l; }
    else                 { Xh_ = d_h1h; Xl_ = d_h1l; }
    __nv_bfloat16* outh = (outsel == 1) ? d_h0h : d_h1h;
    __nv_bfloat16* outl = (outsel == 1) ? d_h0l : d_h1l;
    float* outf = (outsel == 1) ? d_h0f : d_h1f;
    const __nv_bfloat16* WTh = d_WTh[layer];
    const __nv_bfloat16* WTl = d_WTl[layer];

    extern __shared__ __align__(16) __nv_bfloat16 sm[];

    int tid  = threadIdx.x;
    int lane = tid & 31;
    int wid  = tid >> 5;
    int warp_m = wid & 3;
    int warp_n = wid >> 2;
    int rowBase = blockIdx.x * 128;

    float acc[2][8][4];
    #pragma unroll
    for (int mi = 0; mi < 2; mi++)
        #pragma unroll
        for (int ni = 0; ni < 8; ni++)
            #pragma unroll
            for (int q = 0; q < 4; q++) acc[mi][ni][q] = 0.f;

    int a_row = warp_m * 32 + (lane & 15);
    int a_col = (lane >> 4) * 8;
    int b_row = (lane & 15);
    int b_col = warp_n * 64 + (lane >> 4) * 8;

    auto stage = [&](int it) {
        int buf = it & 3;
        const __nv_bfloat16 *sAh, *sAl;
        int kloc;
        if (it < 8) { sAh = d_aggh; sAl = d_aggl; kloc = it * 16; }
        else        { sAh = Xh_;    sAl = Xl_;    kloc = (it - 8) * 16; }
        #pragma unroll
        for (int g = 0; g < 4; g++) {
            int gid = tid + g * 256;
            if (gid < 512) {
                int arr = gid >> 8;
                int r   = (gid & 255) >> 1;
                int j   = gid & 1;
                int grow = rowBase + r;
                const __nv_bfloat16* s = (arr ? sAl : sAh) + (size_t)grow * C + kloc + j * 8;
                uint32_t dst = smem_u32(&sm[(arr ? OFF_AL(buf) : OFF_AH(buf)) + r * ASTR + j * 8]);
                cpa16(dst, s, grow < N_NODES);
            } else {
                int g2  = gid - 512;
                int arr = g2 >> 8;
                int r   = (g2 & 255) >> 4;
                int j   = g2 & 15;
                const __nv_bfloat16* s = (arr ? WTl : WTh) + (it * 16 + r) * 128 + j * 8;
                uint32_t dst = smem_u32(&sm[(arr ? OFF_WL(buf) : OFF_WH(buf)) + r * WSTR + j * 8]);
                cpa16(dst, s, true);
            }
        }
        asm volatile("cp.async.commit_group;" ::: "memory");
    };

    stage(0); stage(1); stage(2);

    for (int it = 0; it < 16; it++) {
        int buf = it & 3;
        if (it < 13) asm volatile("cp.async.wait_group 2;" ::: "memory");
        else         asm volatile("cp.async.wait_group 0;" ::: "memory");
        __syncthreads();
        if (it + 3 < 16) stage(it + 3);

        const __nv_bfloat16* Ah = &sm[OFF_AH(buf)];
        const __nv_bfloat16* Al = &sm[OFF_AL(buf)];
        const __nv_bfloat16* Wh = &sm[OFF_WH(buf)];
        const __nv_bfloat16* Wl = &sm[OFF_WL(buf)];

        uint32_t ah[2][4], al[2][4];
        #pragma unroll
        for (int mi = 0; mi < 2; mi++) {
            ldmA4(ah[mi], smem_u32(&Ah[(a_row + mi * 16) * ASTR + a_col]));
            ldmA4(al[mi], smem_u32(&Al[(a_row + mi * 16) * ASTR + a_col]));
        }
        uint32_t bh[8][2], bl[8][2];
        #pragma unroll
        for (int np = 0; np < 4; np++) {
            uint32_t t4[4];
            ldmBT4(t4, smem_u32(&Wh[b_row * WSTR + np * 16 + b_col]));
            bh[np * 2][0] = t4[0]; bh[np * 2][1] = t4[1];
            bh[np * 2 + 1][0] = t4[2]; bh[np * 2 + 1][1] = t4[3];
            ldmBT4(t4, smem_u32(&Wl[b_row * WSTR + np * 16 + b_col]));
            bl[np * 2][0] = t4[0]; bl[np * 2][1] = t4[1];
            bl[np * 2 + 1][0] = t4[2]; bl[np * 2 + 1][1] = t4[3];
        }
        #pragma unroll
        for (int mi = 0; mi < 2; mi++)
            #pragma unroll
            for (int ni = 0; ni < 8; ni++) {
                mma16816(acc[mi][ni], ah[mi], bh[ni]);
                mma16816(acc[mi][ni], ah[mi], bl[ni]);
                mma16816(acc[mi][ni], al[mi], bh[ni]);
            }
    }

    // ---- epilogue: bias + relu + split + store (hi/lo + fp32 copy) ----------
    int orow = rowBase + warp_m * 32 + (lane >> 2);
    #pragma unroll
    for (int mi = 0; mi < 2; mi++) {
        #pragma unroll
        for (int ni = 0; ni < 8; ni++) {
            int cc = warp_n * 64 + ni * 8 + (lane & 3) * 2;
            float b0 = __ldg(&bias[cc]);
            float b1 = __ldg(&bias[cc + 1]);
            int r0 = orow + mi * 16;
            if (r0 < N_NODES) {
                float vx = fmaxf(acc[mi][ni][0] + b0, 0.f);
                float vy = fmaxf(acc[mi][ni][1] + b1, 0.f);
                __nv_bfloat16 hx, lx, hy, ly;
                split_bf16(vx, hx, lx); split_bf16(vy, hy, ly);
                *(__nv_bfloat162*)&outh[(size_t)r0 * C + cc] = __halves2bfloat162(hx, hy);
                *(__nv_bfloat162*)&outl[(size_t)r0 * C + cc] = __halves2bfloat162(lx, ly);
                *(float2*)&outf[(size_t)r0 * C + cc] = make_float2(vx, vy);
            }
            int r1 = r0 + 8;
            if (r1 < N_NODES) {
                float vx = fmaxf(acc[mi][ni][2] + b0, 0.f);
                float vy = fmaxf(acc[mi][ni][3] + b1, 0.f);
                __nv_bfloat16 hx, lx, hy, ly;
                split_bf16(vx, hx, lx); split_bf16(vy, hy, ly);
                *(__nv_bfloat162*)&outh[(size_t)r1 * C + cc] = __halves2bfloat162(hx, hy);
                *(__nv_bfloat162*)&outl[(size_t)r1 * C + cc] = __halves2bfloat162(lx, ly);
                *(float2*)&outf[(size_t)r1 * C + cc] = make_float2(vx, vy);
            }
        }
    }
}

// ---------------- graph mean pooling -----------------------------------------
__global__ void k_pool(const int* __restrict__ batch) {
    int n = blockIdx.x;
    int c = threadIdx.x;
    int g = batch[n];
    atomicAdd(&d_gsum[g * C + c], d_h1f[(size_t)n * C + c]);
    if (c == 0) atomicAdd(&d_gcnt[g], 1.0f);
}

// ---------------- classifier --------------------------------------------------
__global__ void k_final(const int* __restrict__ root,
                        const float* __restrict__ wcls,
                        const float* __restrict__ bcls,
                        float* __restrict__ out)
{
    int g = blockIdx.x;
    int c = threadIdx.x;
    int rn = root[g];
    float rv = d_h1f[(size_t)rn * C + c];
    float gm = d_gsum[g * C + c] / fmaxf(d_gcnt[g], 1.0f);
    __shared__ float red[2][4];
    float p0 = rv * wcls[0 * 256 + c] + gm * wcls[0 * 256 + 128 + c];
    float p1 = rv * wcls[1 * 256 + c] + gm * wcls[1 * 256 + 128 + c];
    #pragma unroll
    for (int off = 16; off > 0; off >>= 1) {
        p0 += __shfl_down_sync(0xffffffffu, p0, off);
        p1 += __shfl_down_sync(0xffffffffu, p1, off);
    }
    if ((c & 31) == 0) { red[0][c >> 5] = p0; red[1][c >> 5] = p1; }
    __syncthreads();
    if (c == 0) {
        out[g * 2 + 0] = red[0][0] + red[0][1] + red[0][2] + red[0][3] + bcls[0];
        out[g * 2 + 1] = red[1][0] + red[1][1] + red[1][2] + red[1][3] + bcls[1];
    }
}

// ---------------- launch ------------------------------------------------------
extern "C" void kernel_launch(void* const* d_in, const int* in_sizes, int n_in,
                              void* d_out, int out_size)
{
    const float* x     = (const float*)d_in[0];
    const int*   eidx  = (const int*)d_in[1];
    const int*   src   = eidx;
    const int*   tgt   = eidx + N_EDGES;
    const int*   root  = (const int*)d_in[2];
    const int*   batch = (const int*)d_in[3];
    const float* wl[4] = {(const float*)d_in[4],  (const float*)d_in[7],
                          (const float*)d_in[10], (const float*)d_in[13]};
    const float* bl[4] = {(const float*)d_in[5],  (const float*)d_in[8],
                          (const float*)d_in[11], (const float*)d_in[14]};
    const float* wr[4] = {(const float*)d_in[6],  (const float*)d_in[9],
                          (const float*)d_in[12], (const float*)d_in[15]};
    const float* wcls  = (const float*)d_in[16];
    const float* bcls  = (const float*)d_in[17];
    float* out = (float*)d_out;

    (void)in_sizes; (void)n_in; (void)out_size;

    static bool attr_set = false;
    static void *p_deg = nullptr, *p_fill = nullptr, *p_gsum = nullptr, *p_gcnt = nullptr;
    if (!attr_set) {
        cudaFuncSetAttribute(k_gemm, cudaFuncAttributeMaxDynamicSharedMemorySize, GEMM_SMEM_B);
        cudaGetSymbolAddress(&p_deg,  d_deg);
        cudaGetSymbolAddress(&p_fill, d_fill);
        cudaGetSymbolAddress(&p_gsum, d_gsum);
        cudaGetSymbolAddress(&p_gcnt, d_gcnt);
        attr_set = true;
    }

    cudaMemsetAsync(p_deg,  0, N_NODES * sizeof(int));
    cudaMemsetAsync(p_fill, 0, N_NODES * sizeof(int));
    cudaMemsetAsync(p_gsum, 0, N_GRAPHS * C * sizeof(float));
    cudaMemsetAsync(p_gcnt, 0, N_GRAPHS * sizeof(float));

    // 1-3: structure build
    k_prep<<<HB + XB + WB, 256>>>(tgt, x,
                                  wl[0], wr[0], wl[1], wr[1],
                                  wl[2], wr[2], wl[3], wr[3]);
    k_scan<<<1, 1024>>>();
    k_fill<<<(N_EDGES + 255) / 256, 256>>>(src, tgt);
    // 4: alignment no-op so ncu (-s 5 -c 1) captures k_gemm as launch #6
    k_nop<<<1, 32>>>();

    const int GEMM_GRID = (N_NODES + 127) / 128;   // 391
    const int AGG_GRID  = (N_NODES + 7) / 8;       // 6250

    // 5-12: layers
    k_agg<<<AGG_GRID, 256>>>(x, 0);
    k_gemm<<<GEMM_GRID, 256, GEMM_SMEM_B>>>(0, 1, 0, bl[0]);
    k_agg<<<AGG_GRID, 256>>>(x, 1);
    k_gemm<<<GEMM_GRID, 256, GEMM_SMEM_B>>>(1, 2, 1, bl[1]);
    k_agg<<<AGG_GRID, 256>>>(x, 2);
    k_gemm<<<GEMM_GRID, 256, GEMM_SMEM_B>>>(2, 1, 2, bl[2]);
    k_agg<<<AGG_GRID, 256>>>(x, 1);
    k_gemm<<<GEMM_GRID, 256, GEMM_SMEM_B>>>(1, 2, 3, bl[3]);

    // readout
    k_pool<<<N_NODES, 128>>>(batch);
    k_final<<<N_GRAPHS, 128>>>(root, wcls, bcls, out);
}